// round 12
// baseline (speedup 1.0000x reference)
#include <cuda_runtime.h>
#include <math.h>
#include <stdint.h>

// Problem constants
#define T_STEPS 512
#define NBATCH  1024
#define IDIM    64
#define RDIM    256
#define NCTA    128
#define NTHR    512
#define BM      64   // batch rows per CTA
#define BN      32   // output cols per CTA

typedef unsigned long long u64;

// -------- global scratch --------
// Activations in per-row-tile k-major pair-packed layout:
//   elem(tile bi, k, row r=2*pl+e) at base(bi) + k*64 + pl*2 + e
__device__ float g_h[NBATCH * RDIM];        // [16][256][32][2]
__device__ float g_cat[NBATCH * 2 * RDIM];  // [16][512][32][2]
__device__ float g_m[NBATCH * RDIM];        // [16][256][32][2]
__device__ float g_r1p[32 * NBATCH];        // regressor partials [bj*4+wc][1024]
__device__ unsigned g_bar_count = 0;
__device__ unsigned g_bar_gen = 0;

// -------- packed f32x2 helpers --------
__device__ __forceinline__ u64 dup2(float w) {
    u64 r; asm("mov.b64 %0, {%1, %1};" : "=l"(r) : "f"(w)); return r;
}
__device__ __forceinline__ void ffma2(u64& d, u64 a, u64 b) {
    asm("fma.rn.f32x2 %0, %1, %2, %0;" : "+l"(d) : "l"(a), "l"(b));
}
__device__ __forceinline__ void fadd2(u64& d, u64 o) {
    asm("add.rn.f32x2 %0, %0, %1;" : "+l"(d) : "l"(o));
}
__device__ __forceinline__ float2 unpack2(u64 v) {
    float2 f; asm("mov.b64 {%0, %1}, %2;" : "=f"(f.x), "=f"(f.y) : "l"(v)); return f;
}

// -------- cp.async helpers (L1-bypass for cross-CTA coherence) --------
__device__ __forceinline__ void cp_async16(float* sdst, const float* gsrc) {
    unsigned s = (unsigned)__cvta_generic_to_shared(sdst);
    asm volatile("cp.async.cg.shared.global [%0], [%1], 16;" :: "r"(s), "l"(gsrc));
}
__device__ __forceinline__ void cp_commit() { asm volatile("cp.async.commit_group;"); }
template <int N>
__device__ __forceinline__ void cp_wait() {
    asm volatile("cp.async.wait_group %0;" :: "n"(N));
}

// -------- grid-wide sense-reversing barrier --------
__device__ __forceinline__ void grid_barrier() {
    __threadfence();
    __syncthreads();
    if (threadIdx.x == 0) {
        unsigned g = *((volatile unsigned*)&g_bar_gen);
        unsigned old = atomicAdd(&g_bar_count, 1u);
        if (old == NCTA - 1) {
            g_bar_count = 0;
            __threadfence();
            *((volatile unsigned*)&g_bar_gen) = g + 1;
        } else {
            unsigned cur;
            do {
                asm volatile("ld.acquire.gpu.global.u32 %0, [%1];"
                             : "=r"(cur) : "l"(&g_bar_gen));
            } while (cur == g);
        }
    }
    __syncthreads();
}

// -------- stage one contiguous 16KB chunk (64k x 64 floats), one group ------
__device__ __forceinline__ void stage16k(float* buf, const float* __restrict__ g) {
    int u = threadIdx.x;
    #pragma unroll
    for (int i = 0; i < 2; i++, u += NTHR)
        cp_async16(buf + u * 4, g + u * 4);
    cp_commit();
}

// -------- compute this team's half (32 k) of a staged 64-k chunk -----------
// As: [k][pair][e]. Thread: 2 pairs x 2 cols. acc: p0c0, p1c0, p0c1, p1c1.
template <bool FUSE2>
__device__ __forceinline__ void compute_chunk(
    const float* __restrict__ As,      // + team*2048 applied by caller
    const float* __restrict__ w1p,     // + team*1024 applied by caller
    const float* __restrict__ w2p,
    u64 a1[4], u64 a2[4], int aoff, int cc2)
{
    #pragma unroll 8
    for (int k2 = 0; k2 < 16; k2++) {
        const float* arow = As + k2 * 128 + aoff;
        ulonglong2 A0 = *(const ulonglong2*)(arow);        // k even: 2 pairs
        ulonglong2 A1 = *(const ulonglong2*)(arow + 64);   // k odd
        float4 w = *(const float4*)(w1p + k2 * 64 + cc2);
        u64 w00 = dup2(w.x), w01 = dup2(w.y), w10 = dup2(w.z), w11 = dup2(w.w);
        ffma2(a1[0], A0.x, w00); ffma2(a1[1], A0.y, w00);
        ffma2(a1[2], A0.x, w10); ffma2(a1[3], A0.y, w10);
        ffma2(a1[0], A1.x, w01); ffma2(a1[1], A1.y, w01);
        ffma2(a1[2], A1.x, w11); ffma2(a1[3], A1.y, w11);
        if constexpr (FUSE2) {
            float4 v = *(const float4*)(w2p + k2 * 64 + cc2);
            u64 v00 = dup2(v.x), v01 = dup2(v.y), v10 = dup2(v.z), v11 = dup2(v.w);
            ffma2(a2[0], A0.x, v00); ffma2(a2[1], A0.y, v00);
            ffma2(a2[2], A0.x, v10); ffma2(a2[3], A0.y, v10);
            ffma2(a2[0], A1.x, v01); ffma2(a2[1], A1.y, v01);
            ffma2(a2[2], A1.x, v11); ffma2(a2[3], A1.y, v11);
        }
    }
}

// -------- pipelined GEMM over NCH 64k chunks (3-buffer ring, 1 sync/chunk) --
template <int NCH, bool FUSE2>
__device__ __forceinline__ void gemm_pipe(
    const float* __restrict__ gbase,
    const float* __restrict__ W1, const float* __restrict__ W2,
    float* bufs, u64 a1[4], u64 a2[4], int aoff, int cc2, int team)
{
    const int koffA = team * 2048;   // 16 k2-windows * 128 floats
    const int koffW = team * 1024;   // 16 k2-windows * 64 floats
    stage16k(bufs,        gbase);
    stage16k(bufs + 4096, gbase + 4096);
    #pragma unroll
    for (int i = 0; i < NCH; i++) {
        if (i < NCH - 1) cp_wait<1>(); else cp_wait<0>();
        __syncthreads();
        if (i + 2 < NCH) stage16k(bufs + ((i + 2) % 3) * 4096, gbase + (i + 2) * 4096);
        compute_chunk<FUSE2>(bufs + (i % 3) * 4096 + koffA,
                             W1 + i * 2048 + koffW, W2 + i * 2048 + koffW,
                             a1, a2, aoff, cc2);
    }
}

// -------- team partial-sum reduction through an idle smem ring slot ---------
template <int N>
__device__ __forceinline__ void team_reduce(u64* acc, float* redf, int team, int tidB)
{
    u64* red = (u64*)redf;
    if (team) {
        #pragma unroll
        for (int j = 0; j < N; j++) red[j * 256 + tidB] = acc[j];
    }
    __syncthreads();
    if (!team) {
        #pragma unroll
        for (int j = 0; j < N; j++) fadd2(acc[j], red[j * 256 + tidB]);
    }
    __syncthreads();
}

__global__ void __launch_bounds__(NTHR, 1)
recurrent_kernel(const float* __restrict__ inputs,
                 const float* __restrict__ Whp, const float* __restrict__ bhp,
                 const float* __restrict__ Wcp, const float* __restrict__ bcp,
                 const float* __restrict__ Wm,  const float* __restrict__ bm,
                 const float* __restrict__ Whpost, const float* __restrict__ bhpost,
                 const float* __restrict__ Wr1, const float* __restrict__ br1,
                 const float* __restrict__ Wr2, const float* __restrict__ br2,
                 float* __restrict__ out)
{
    extern __shared__ float smem[];
    float* Whp_p    = smem;                 // 8192  (256k packed)
    float* Wr1_p    = Whp_p    + 8192;      // 8192
    float* Wm_p     = Wr1_p    + 8192;      // 16384 (512k packed)
    float* Whpost_p = Wm_p     + 16384;     // 8192
    float* Wcp_p    = Whpost_p + 8192;      // 2048  (64k packed)
    float* bias_s   = Wcp_p    + 2048;      // 192
    float* bufs     = bias_s   + 192;       // 3 x 4096

    const int tid  = threadIdx.x;
    const int team = tid >> 8;         // 0 or 1 (k-split team)
    const int tidB = tid & 255;        // index within team
    const int wid8 = tidB >> 5;        // team-local warp 0..7
    const int lane = tid & 31;
    const int wr = wid8 & 1;           // row half (32 rows)
    const int wc = wid8 >> 1;          // col group 0..3 (8 cols each)
    const int lr = lane >> 2;          // lane row 0..7
    const int lc = lane & 3;           // lane col 0..3
    const int plbase = wr * 16 + lr * 2;   // first local pair (of 2)
    const int cc     = wc * 8 + lc * 2;    // first local col (of 2)
    const int aoff   = plbase * 2;
    const int cc2    = cc * 2;

    const int bi   = blockIdx.x >> 3;   // row tile 0..15
    const int bj   = blockIdx.x & 7;    // col tile 0..7
    const int row0 = bi * BM;
    const int c0   = bj * BN;

    const int hbase   = bi * (RDIM * BM);       // 16384 floats per tile
    const int catbase = bi * (2 * RDIM * BM);   // 32768

    // ---- build packed weight slices: Wp[(k>>1)*64 + col*2 + (k&1)] ----
    for (int i = tid; i < 256 * BN; i += NTHR) {
        int k = i >> 5, col = i & 31;
        int d = (k >> 1) * 64 + col * 2 + (k & 1);
        Whp_p[d]    = Whp[k * RDIM + c0 + col];
        Wr1_p[d]    = Wr1[k * RDIM + c0 + col];
        Whpost_p[d] = Whpost[k * RDIM + c0 + col];
    }
    for (int i = tid; i < 512 * BN; i += NTHR) {
        int k = i >> 5, col = i & 31;
        Wm_p[(k >> 1) * 64 + col * 2 + (k & 1)] = Wm[k * RDIM + c0 + col];
    }
    for (int i = tid; i < 64 * BN; i += NTHR) {
        int k = i >> 5, col = i & 31;
        Wcp_p[(k >> 1) * 64 + col * 2 + (k & 1)] = Wcp[k * RDIM + c0 + col];
    }
    if (tid < 32) {
        bias_s[tid]       = bhp[c0 + tid];
        bias_s[32 + tid]  = bcp[c0 + tid];
        bias_s[64 + tid]  = bm[c0 + tid];
        bias_s[96 + tid]  = bhpost[c0 + tid];
        bias_s[128 + tid] = br1[c0 + tid];
        bias_s[160 + tid] = Wr2[c0 + tid];
    }
    const float br2v = __ldg(br2);
    __syncthreads();

    for (int t = 0; t < T_STEPS; t++) {
        // ================= Phase A =================
        // ---- stage x_t (row-major, XOR-swizzled 16B slots) into buf0 ----
        {
            const float* xg = inputs + (size_t)t * NBATCH * IDIM + (size_t)row0 * IDIM;
            int u = tid;
            #pragma unroll
            for (int i = 0; i < 2; i++, u += NTHR) {
                int r = u >> 4, s = u & 15;
                cp_async16(bufs + r * 64 + ((s ^ ((r >> 2) & 7)) << 2),
                           xg + r * 64 + s * 4);
            }
            cp_commit();
            cp_wait<0>();
            __syncthreads();
        }
        // ---- S0: tcp = tanh(x @ Wcp + bcp), team-split over k ----
        {
            float aS[4];
            #pragma unroll
            for (int j = 0; j < 4; j++) aS[j] = team ? 0.f : bias_s[16 + cc - cc + 32 + cc] * 0.f + bias_s[32 + cc];
            // (team A carries bias; team B starts at 0)
            if (team) { aS[0] = aS[1] = aS[2] = aS[3] = 0.f; }
            else { aS[0] = aS[1] = bias_s[32 + cc]; aS[2] = aS[3] = bias_s[32 + cc + 1]; }
            // aS layout: [0]=row j0 c0, [1]=row j1 c0 ... use [rowj][col] flattened below
            float aT[4][2];
            #pragma unroll
            for (int j = 0; j < 4; j++) {
                aT[j][0] = team ? 0.f : bias_s[32 + cc];
                aT[j][1] = team ? 0.f : bias_s[32 + cc + 1];
            }
            #pragma unroll
            for (int k4i = 0; k4i < 8; k4i++) {
                int k4 = team * 8 + k4i;
                float4 wA = *(const float4*)(Wcp_p + (2 * k4) * 64 + cc2);
                float4 wB = *(const float4*)(Wcp_p + (2 * k4 + 1) * 64 + cc2);
                #pragma unroll
                for (int j = 0; j < 4; j++) {
                    int r = wr * 32 + lr * 4 + j;
                    float4 a = *(const float4*)(bufs + r * 64 + ((k4 ^ ((r >> 2) & 7)) << 2));
                    aT[j][0] = fmaf(a.x, wA.x, aT[j][0]);
                    aT[j][0] = fmaf(a.y, wA.y, aT[j][0]);
                    aT[j][0] = fmaf(a.z, wB.x, aT[j][0]);
                    aT[j][0] = fmaf(a.w, wB.y, aT[j][0]);
                    aT[j][1] = fmaf(a.x, wA.z, aT[j][1]);
                    aT[j][1] = fmaf(a.y, wA.w, aT[j][1]);
                    aT[j][1] = fmaf(a.z, wB.z, aT[j][1]);
                    aT[j][1] = fmaf(a.w, wB.w, aT[j][1]);
                }
            }
            // reduce team partials through buf1
            float* redf = bufs + 4096;
            if (team) {
                #pragma unroll
                for (int j = 0; j < 4; j++) {
                    redf[(2 * j) * 256 + tidB]     = aT[j][0];
                    redf[(2 * j + 1) * 256 + tidB] = aT[j][1];
                }
            }
            __syncthreads();
            if (!team) {
                #pragma unroll
                for (int j = 0; j < 4; j++) {
                    aT[j][0] += redf[(2 * j) * 256 + tidB];
                    aT[j][1] += redf[(2 * j + 1) * 256 + tidB];
                }
            }
            __syncthreads();
            if (!team) {
                #pragma unroll
                for (int ci = 0; ci < 2; ci++) {
                    size_t xcol = catbase + (size_t)(RDIM + c0 + cc + ci) * 64;
                    *(float2*)(g_cat + xcol + plbase * 2)
                        = make_float2(tanhf(aT[0][ci]), tanhf(aT[1][ci]));
                    *(float2*)(g_cat + xcol + (plbase + 1) * 2)
                        = make_float2(tanhf(aT[2][ci]), tanhf(aT[3][ci]));
                }
            }
        }

        if (t > 0) {
            // ---- S1 + S4 fused: a = tanh(h@Whp+bhp); r = h@Wr1+br1 ----
            u64 acc_a[4], acc_r[4];
            if (team) {
                acc_a[0] = acc_a[1] = acc_a[2] = acc_a[3] = 0;
                acc_r[0] = acc_r[1] = acc_r[2] = acc_r[3] = 0;
            } else {
                acc_a[0] = acc_a[1] = dup2(bias_s[cc]);
                acc_a[2] = acc_a[3] = dup2(bias_s[cc + 1]);
                acc_r[0] = acc_r[1] = dup2(bias_s[128 + cc]);
                acc_r[2] = acc_r[3] = dup2(bias_s[128 + cc + 1]);
            }
            gemm_pipe<4, true>(g_h + hbase, Whp_p, Wr1_p, bufs,
                               acc_a, acc_r, aoff, cc2, team);
            // reduce 8 accs through ring slot (4%3)=1
            {
                float* redf = bufs + 4096;
                u64* red = (u64*)redf;
                if (team) {
                    #pragma unroll
                    for (int j = 0; j < 4; j++) {
                        red[j * 256 + tidB]       = acc_a[j];
                        red[(4 + j) * 256 + tidB] = acc_r[j];
                    }
                }
                __syncthreads();
                if (!team) {
                    #pragma unroll
                    for (int j = 0; j < 4; j++) {
                        fadd2(acc_a[j], red[j * 256 + tidB]);
                        fadd2(acc_r[j], red[(4 + j) * 256 + tidB]);
                    }
                }
                __syncthreads();
            }
            if (!team) {
                #pragma unroll
                for (int ci = 0; ci < 2; ci++) {
                    size_t acol = catbase + (size_t)(c0 + cc + ci) * 64;
                    #pragma unroll
                    for (int p = 0; p < 2; p++) {
                        float2 f = unpack2(acc_a[ci * 2 + p]);
                        *(float2*)(g_cat + acol + (plbase + p) * 2)
                            = make_float2(tanhf(f.x), tanhf(f.y));
                    }
                }
                // S4 partial: v[row] = sum_cols relu(r)*Wr2[col]
                float w20 = bias_s[160 + cc], w21 = bias_s[160 + cc + 1];
                float2 r00 = unpack2(acc_r[0]), r10 = unpack2(acc_r[1]);
                float2 r01 = unpack2(acc_r[2]), r11 = unpack2(acc_r[3]);
                float v0 = fmaxf(r00.x, 0.f) * w20 + fmaxf(r01.x, 0.f) * w21;
                float v1 = fmaxf(r00.y, 0.f) * w20 + fmaxf(r01.y, 0.f) * w21;
                float v2 = fmaxf(r10.x, 0.f) * w20 + fmaxf(r11.x, 0.f) * w21;
                float v3 = fmaxf(r10.y, 0.f) * w20 + fmaxf(r11.y, 0.f) * w21;
                #pragma unroll
                for (int off = 1; off <= 2; off <<= 1) {
                    v0 += __shfl_xor_sync(0xffffffffu, v0, off);
                    v1 += __shfl_xor_sync(0xffffffffu, v1, off);
                    v2 += __shfl_xor_sync(0xffffffffu, v2, off);
                    v3 += __shfl_xor_sync(0xffffffffu, v3, off);
                }
                if (lc == 0)
                    *(float4*)(g_r1p + (size_t)(bj * 4 + wc) * NBATCH + row0 + wr * 32 + lr * 4)
                        = make_float4(v0, v1, v2, v3);
            }
        } else if (!team) {
            // h0 == 0 -> cat[:,0:256] = tanh(bhp)
            #pragma unroll
            for (int ci = 0; ci < 2; ci++) {
                float av = tanhf(bias_s[cc + ci]);
                size_t acol = catbase + (size_t)(c0 + cc + ci) * 64;
                *(float2*)(g_cat + acol + plbase * 2)       = make_float2(av, av);
                *(float2*)(g_cat + acol + (plbase + 1) * 2) = make_float2(av, av);
            }
        }
        grid_barrier();

        // ================= Phase B: m = tanh(cat @ Wm + bm) =================
        // finalize out[t-1] first so its L2 latency overlaps the GEMM
        if (bj == 0 && t > 0 && tid < BM) {
            int n = row0 + tid;
            float s = br2v;
            #pragma unroll 8
            for (int q = 0; q < 32; q++)
                s += __ldcg(&g_r1p[(size_t)q * NBATCH + n]);
            out[(size_t)(t - 1) * NBATCH + n] = s;
        }
        {
            u64 acc[4];
            if (team) { acc[0] = acc[1] = acc[2] = acc[3] = 0; }
            else {
                acc[0] = acc[1] = dup2(bias_s[64 + cc]);
                acc[2] = acc[3] = dup2(bias_s[64 + cc + 1]);
            }
            gemm_pipe<8, false>(g_cat + catbase, Wm_p, Wm_p, bufs,
                                acc, acc, aoff, cc2, team);
            team_reduce<4>(acc, bufs + 2 * 4096, team, tidB);   // slot (8%3)=2
            if (!team) {
                #pragma unroll
                for (int ci = 0; ci < 2; ci++) {
                    size_t mcol = hbase + (size_t)(c0 + cc + ci) * 64;
                    #pragma unroll
                    for (int p = 0; p < 2; p++) {
                        float2 f = unpack2(acc[ci * 2 + p]);
                        *(float2*)(g_m + mcol + (plbase + p) * 2)
                            = make_float2(tanhf(f.x), tanhf(f.y));
                    }
                }
            }
        }
        grid_barrier();

        // ================= Phase C: h = tanh(m @ Whpost + bhpost) ============
        {
            u64 acc[4];
            if (team) { acc[0] = acc[1] = acc[2] = acc[3] = 0; }
            else {
                acc[0] = acc[1] = dup2(bias_s[96 + cc]);
                acc[2] = acc[3] = dup2(bias_s[96 + cc + 1]);
            }
            gemm_pipe<4, false>(g_m + hbase, Whpost_p, Whpost_p, bufs,
                                acc, acc, aoff, cc2, team);
            team_reduce<4>(acc, bufs + 4096, team, tidB);       // slot (4%3)=1
            if (!team) {
                #pragma unroll
                for (int ci = 0; ci < 2; ci++) {
                    size_t hcol = hbase + (size_t)(c0 + cc + ci) * 64;
                    #pragma unroll
                    for (int p = 0; p < 2; p++) {
                        float2 f = unpack2(acc[ci * 2 + p]);
                        *(float2*)(g_h + hcol + (plbase + p) * 2)
                            = make_float2(tanhf(f.x), tanhf(f.y));
                    }
                }
            }
        }
        grid_barrier();
    }

    // ================= Epilogue: regressor for final step =================
    {
        u64 acc[4];
        if (team) { acc[0] = acc[1] = acc[2] = acc[3] = 0; }
        else {
            acc[0] = acc[1] = dup2(bias_s[128 + cc]);
            acc[2] = acc[3] = dup2(bias_s[128 + cc + 1]);
        }
        gemm_pipe<4, false>(g_h + hbase, Wr1_p, Wr1_p, bufs, acc, acc, aoff, cc2, team);
        team_reduce<4>(acc, bufs + 4096, team, tidB);
        if (!team) {
            float w20 = bias_s[160 + cc], w21 = bias_s[160 + cc + 1];
            float2 r00 = unpack2(acc[0]), r10 = unpack2(acc[1]);
            float2 r01 = unpack2(acc[2]), r11 = unpack2(acc[3]);
            float v0 = fmaxf(r00.x, 0.f) * w20 + fmaxf(r01.x, 0.f) * w21;
            float v1 = fmaxf(r00.y, 0.f) * w20 + fmaxf(r01.y, 0.f) * w21;
            float v2 = fmaxf(r10.x, 0.f) * w20 + fmaxf(r11.x, 0.f) * w21;
            float v3 = fmaxf(r10.y, 0.f) * w20 + fmaxf(r11.y, 0.f) * w21;
            #pragma unroll
            for (int off = 1; off <= 2; off <<= 1) {
                v0 += __shfl_xor_sync(0xffffffffu, v0, off);
                v1 += __shfl_xor_sync(0xffffffffu, v1, off);
                v2 += __shfl_xor_sync(0xffffffffu, v2, off);
                v3 += __shfl_xor_sync(0xffffffffu, v3, off);
            }
            if (lc == 0)
                *(float4*)(g_r1p + (size_t)(bj * 4 + wc) * NBATCH + row0 + wr * 32 + lr * 4)
                    = make_float4(v0, v1, v2, v3);
        }
    }
    grid_barrier();
    if (bj == 0 && tid < BM) {
        int n = row0 + tid;
        float s = br2v;
        #pragma unroll 8
        for (int q = 0; q < 32; q++)
            s += __ldcg(&g_r1p[(size_t)q * NBATCH + n]);
        out[(size_t)(T_STEPS - 1) * NBATCH + n] = s;
    }
}

extern "C" void kernel_launch(void* const* d_in, const int* in_sizes, int n_in,
                              void* d_out, int out_size)
{
    (void)in_sizes; (void)n_in; (void)out_size;
    const float* inputs = (const float*)d_in[0];
    const float* Whp    = (const float*)d_in[1];
    const float* bhp    = (const float*)d_in[2];
    const float* Wcp    = (const float*)d_in[3];
    const float* bcp    = (const float*)d_in[4];
    const float* Wm     = (const float*)d_in[5];
    const float* bm     = (const float*)d_in[6];
    const float* Whpost = (const float*)d_in[7];
    const float* bhpost = (const float*)d_in[8];
    const float* Wr1    = (const float*)d_in[9];
    const float* br1    = (const float*)d_in[10];
    const float* Wr2    = (const float*)d_in[11];
    const float* br2    = (const float*)d_in[12];
    float* out = (float*)d_out;

    // smem: packed weights 43008 + bias 192 + 3x4096 staging = 55488 floats
    //     = 221,952 B per CTA -> 1 CTA/SM
    const size_t smem_bytes = (size_t)55488 * sizeof(float);
    cudaFuncSetAttribute(recurrent_kernel,
                         cudaFuncAttributeMaxDynamicSharedMemorySize,
                         (int)smem_bytes);

    recurrent_kernel<<<NCTA, NTHR, smem_bytes>>>(
        inputs, Whp, bhp, Wcp, bcp, Wm, bm, Whpost, bhpost,
        Wr1, br1, Wr2, br2, out);
}

// round 13
// speedup vs baseline: 1.5697x; 1.5697x over previous
#include <cuda_runtime.h>
#include <math.h>
#include <stdint.h>

// Problem constants
#define T_STEPS 512
#define NBATCH  1024
#define IDIM    64
#define RDIM    256
#define NCTA    128
#define NTHR    256
#define BM      64   // batch rows per CTA
#define BN      32   // output cols per CTA
#define NGRP    16   // row groups (8 CTAs each)

typedef unsigned long long u64;

// -------- global scratch --------
// Activations in per-row-tile k-major pair-packed layout:
//   elem(tile bi, k, row r=2*pl+e) at  base(bi) + k*64 + pl*2 + e
__device__ float g_h[NBATCH * RDIM];        // [16][256][32][2]
__device__ float g_cat[NBATCH * 2 * RDIM];  // [16][512][32][2]
__device__ float g_m[NBATCH * RDIM];        // [16][256][32][2]
__device__ float g_r1p2[32 * NBATCH];       // regressor partials [bj*4+wc][1024]
// per-row-group barrier state, one 128B line per group
__device__ unsigned g_grp_bar[NGRP * 32];   // [g*32+0]=count, [g*32+16]=gen

// -------- packed f32x2 helpers --------
__device__ __forceinline__ u64 dup2(float w) {
    u64 r; asm("mov.b64 %0, {%1, %1};" : "=l"(r) : "f"(w)); return r;
}
__device__ __forceinline__ void ffma2(u64& d, u64 a, u64 b) {
    asm("fma.rn.f32x2 %0, %1, %2, %0;" : "+l"(d) : "l"(a), "l"(b));
}
__device__ __forceinline__ float2 unpack2(u64 v) {
    float2 f; asm("mov.b64 {%0, %1}, %2;" : "=f"(f.x), "=f"(f.y) : "l"(v)); return f;
}

// -------- cp.async helpers (L1-bypass for cross-CTA coherence) --------
__device__ __forceinline__ void cp_async16(float* sdst, const float* gsrc) {
    unsigned s = (unsigned)__cvta_generic_to_shared(sdst);
    asm volatile("cp.async.cg.shared.global [%0], [%1], 16;" :: "r"(s), "l"(gsrc));
}
__device__ __forceinline__ void cp_commit() { asm volatile("cp.async.commit_group;"); }
template <int N>
__device__ __forceinline__ void cp_wait() {
    asm volatile("cp.async.wait_group %0;" :: "n"(N));
}

// -------- per-row-group sense-reversing barrier (8 CTAs) --------
__device__ __forceinline__ void group_barrier(int grp) {
    __threadfence();
    __syncthreads();
    if (threadIdx.x == 0) {
        unsigned* cnt = &g_grp_bar[grp * 32];
        unsigned* gen = &g_grp_bar[grp * 32 + 16];
        unsigned g = *((volatile unsigned*)gen);
        unsigned old = atomicAdd(cnt, 1u);
        if (old == 7) {                       // last of the 8 group CTAs
            *cnt = 0;
            __threadfence();
            *((volatile unsigned*)gen) = g + 1;
        } else {
            unsigned cur;
            do {
                asm volatile("ld.acquire.gpu.global.u32 %0, [%1];"
                             : "=r"(cur) : "l"(gen));
            } while (cur == g);
        }
    }
    __syncthreads();
}

// -------- stage one contiguous 16KB chunk (64k x 64 floats), one group ------
__device__ __forceinline__ void stage16k(float* buf, const float* __restrict__ g) {
    int u = threadIdx.x;
    #pragma unroll
    for (int i = 0; i < 4; i++, u += NTHR)
        cp_async16(buf + u * 4, g + u * 4);
    cp_commit();
}

// -------- compute one staged 64k chunk --------
// As: [k][pair][e] (64 k-rows x 64 floats). Thread: pairs plbase..+1, cols cc..+1.
// acc layout: a[0]=p0c0, a[1]=p1c0, a[2]=p0c1, a[3]=p1c1 (packed over rows).
template <bool FUSE2>
__device__ __forceinline__ void compute_chunk(
    const float* __restrict__ As,
    const float* __restrict__ w1p, const float* __restrict__ w2p,
    u64 a1[4], u64 a2[4], int plbase, int cc)
{
    #pragma unroll 8
    for (int k2 = 0; k2 < 32; k2++) {
        const float* arow = As + (k2 * 2) * 64 + plbase * 2;
        ulonglong2 A0 = *(const ulonglong2*)(arow);        // k even: pairs pl, pl+1
        ulonglong2 A1 = *(const ulonglong2*)(arow + 64);   // k odd
        float4 w = *(const float4*)(w1p + k2 * 64 + cc * 2);
        u64 w00 = dup2(w.x), w01 = dup2(w.y), w10 = dup2(w.z), w11 = dup2(w.w);
        ffma2(a1[0], A0.x, w00); ffma2(a1[1], A0.y, w00);
        ffma2(a1[2], A0.x, w10); ffma2(a1[3], A0.y, w10);
        ffma2(a1[0], A1.x, w01); ffma2(a1[1], A1.y, w01);
        ffma2(a1[2], A1.x, w11); ffma2(a1[3], A1.y, w11);
        if constexpr (FUSE2) {
            float4 v = *(const float4*)(w2p + k2 * 64 + cc * 2);
            u64 v00 = dup2(v.x), v01 = dup2(v.y), v10 = dup2(v.z), v11 = dup2(v.w);
            ffma2(a2[0], A0.x, v00); ffma2(a2[1], A0.y, v00);
            ffma2(a2[2], A0.x, v10); ffma2(a2[3], A0.y, v10);
            ffma2(a2[0], A1.x, v01); ffma2(a2[1], A1.y, v01);
            ffma2(a2[2], A1.x, v11); ffma2(a2[3], A1.y, v11);
        }
    }
}

// -------- pipelined GEMM over NCH 64k chunks (3-buffer ring, 1 sync/chunk) ----
template <int NCH, bool FUSE2>
__device__ __forceinline__ void gemm_pipe(
    const float* __restrict__ gbase,
    const float* __restrict__ W1, const float* __restrict__ W2,
    float* bufs, u64 a1[4], u64 a2[4], int plbase, int cc)
{
    stage16k(bufs,        gbase);
    stage16k(bufs + 4096, gbase + 4096);
    #pragma unroll
    for (int i = 0; i < NCH; i++) {
        if (i < NCH - 1) cp_wait<1>(); else cp_wait<0>();
        __syncthreads();
        if (i + 2 < NCH) stage16k(bufs + ((i + 2) % 3) * 4096, gbase + (i + 2) * 4096);
        compute_chunk<FUSE2>(bufs + (i % 3) * 4096, W1 + i * 2048, W2 + i * 2048,
                             a1, a2, plbase, cc);
    }
}

__global__ void __launch_bounds__(NTHR, 1)
recurrent_kernel(const float* __restrict__ inputs,
                 const float* __restrict__ Whp, const float* __restrict__ bhp,
                 const float* __restrict__ Wcp, const float* __restrict__ bcp,
                 const float* __restrict__ Wm,  const float* __restrict__ bm,
                 const float* __restrict__ Whpost, const float* __restrict__ bhpost,
                 const float* __restrict__ Wr1, const float* __restrict__ br1,
                 const float* __restrict__ Wr2, const float* __restrict__ br2,
                 float* __restrict__ out)
{
    extern __shared__ float smem[];
    float* Whp_p    = smem;                 // 8192  (256k packed)
    float* Wr1_p    = Whp_p    + 8192;      // 8192
    float* Wm_p     = Wr1_p    + 8192;      // 16384 (512k packed)
    float* Whpost_p = Wm_p     + 16384;     // 8192
    float* Wcp_p    = Whpost_p + 8192;      // 2048  (64k packed)
    float* bias_s   = Wcp_p    + 2048;      // 192
    float* bufs     = bias_s   + 192;       // 3 x 4096

    const int tid  = threadIdx.x;
    const int wid  = tid >> 5;
    const int lane = tid & 31;
    const int wr = wid & 1;          // row half (32 rows)
    const int wc = wid >> 1;         // col group (8 cols), 0..3
    const int lr = lane >> 2;        // lane row  0..7
    const int lc = lane & 3;         // lane col  0..3
    const int plbase = wr * 16 + lr * 2;   // first local pair (of 2)
    const int cc     = wc * 8 + lc * 2;    // first local col (of 2)

    const int bi   = blockIdx.x >> 3;   // row tile / group 0..15
    const int bj   = blockIdx.x & 7;    // col tile 0..7
    const int row0 = bi * BM;
    const int c0   = bj * BN;

    const int hbase   = bi * (RDIM * BM);       // 16384 floats per tile
    const int catbase = bi * (2 * RDIM * BM);   // 32768
    float* Xs; // alias of bufs+2 for S0

    // ---- build packed weight slices: Wp[(k>>1)*64 + col*2 + (k&1)] ----
    for (int i = tid; i < 256 * BN; i += NTHR) {
        int k = i >> 5, col = i & 31;
        int d = (k >> 1) * 64 + col * 2 + (k & 1);
        Whp_p[d]    = Whp[k * RDIM + c0 + col];
        Wr1_p[d]    = Wr1[k * RDIM + c0 + col];
        Whpost_p[d] = Whpost[k * RDIM + c0 + col];
    }
    for (int i = tid; i < 512 * BN; i += NTHR) {
        int k = i >> 5, col = i & 31;
        Wm_p[(k >> 1) * 64 + col * 2 + (k & 1)] = Wm[k * RDIM + c0 + col];
    }
    for (int i = tid; i < 64 * BN; i += NTHR) {
        int k = i >> 5, col = i & 31;
        Wcp_p[(k >> 1) * 64 + col * 2 + (k & 1)] = Wcp[k * RDIM + c0 + col];
    }
    if (tid < 32) {
        bias_s[tid]       = bhp[c0 + tid];
        bias_s[32 + tid]  = bcp[c0 + tid];
        bias_s[64 + tid]  = bm[c0 + tid];
        bias_s[96 + tid]  = bhpost[c0 + tid];
        bias_s[128 + tid] = br1[c0 + tid];
        bias_s[160 + tid] = Wr2[c0 + tid];
    }
    const float br2v = __ldg(br2);
    __syncthreads();

    for (int t = 0; t < T_STEPS; t++) {
        // ================= Phase A =================
        // stage x_t (row-major, XOR-swizzled slots) into buf2
        Xs = bufs + 2 * 4096;
        {
            const float* xg = inputs + (size_t)t * NBATCH * IDIM + (size_t)row0 * IDIM;
            int u = tid;
            #pragma unroll
            for (int i = 0; i < 4; i++, u += NTHR) {
                int r = u >> 4, s = u & 15;
                cp_async16(Xs + r * 64 + ((s ^ ((r >> 2) & 7)) << 2), xg + r * 64 + s * 4);
            }
            cp_commit();
        }
        if (t > 0) {
            stage16k(bufs,        g_h + hbase);
            stage16k(bufs + 4096, g_h + hbase + 4096);
            cp_wait<2>();
        } else {
            cp_wait<0>();
        }
        __syncthreads();

        // ---- S0: tcp = tanh(x @ Wcp + bcp) -> cat[:, 256:512] (scalar path) ----
        {
            float aS[4][2];
            #pragma unroll
            for (int j = 0; j < 4; j++) {
                aS[j][0] = bias_s[32 + cc];
                aS[j][1] = bias_s[32 + cc + 1];
            }
            #pragma unroll 4
            for (int k4 = 0; k4 < 16; k4++) {
                float4 wA = *(const float4*)(Wcp_p + (2 * k4) * 64 + cc * 2);
                float4 wB = *(const float4*)(Wcp_p + (2 * k4 + 1) * 64 + cc * 2);
                #pragma unroll
                for (int j = 0; j < 4; j++) {
                    int r = wr * 32 + lr * 4 + j;
                    float4 a = *(const float4*)(Xs + r * 64 + ((k4 ^ lr) << 2));
                    aS[j][0] = fmaf(a.x, wA.x, aS[j][0]);
                    aS[j][0] = fmaf(a.y, wA.y, aS[j][0]);
                    aS[j][0] = fmaf(a.z, wB.x, aS[j][0]);
                    aS[j][0] = fmaf(a.w, wB.y, aS[j][0]);
                    aS[j][1] = fmaf(a.x, wA.z, aS[j][1]);
                    aS[j][1] = fmaf(a.y, wA.w, aS[j][1]);
                    aS[j][1] = fmaf(a.z, wB.z, aS[j][1]);
                    aS[j][1] = fmaf(a.w, wB.w, aS[j][1]);
                }
            }
            #pragma unroll
            for (int ci = 0; ci < 2; ci++)
                #pragma unroll
                for (int p = 0; p < 2; p++) {
                    float2 v = make_float2(tanhf(aS[2 * p][ci]), tanhf(aS[2 * p + 1][ci]));
                    *(float2*)(g_cat + catbase + (RDIM + c0 + cc + ci) * 64
                               + (plbase + p) * 2) = v;
                }
        }

        if (t > 0) {
            // ---- S1 + S4 fused: a = tanh(h@Whp+bhp); r1acc = h@Wr1+br1 ----
            u64 acc_a[4], acc_r[4];
            acc_a[0] = acc_a[1] = dup2(bias_s[cc]);
            acc_a[2] = acc_a[3] = dup2(bias_s[cc + 1]);
            acc_r[0] = acc_r[1] = dup2(bias_s[128 + cc]);
            acc_r[2] = acc_r[3] = dup2(bias_s[128 + cc + 1]);
            #pragma unroll
            for (int i = 0; i < 4; i++) {
                if (i < 3) cp_wait<1>(); else cp_wait<0>();
                __syncthreads();
                if (i + 2 < 4) stage16k(bufs + ((i + 2) % 3) * 4096,
                                        g_h + hbase + (i + 2) * 4096);
                compute_chunk<true>(bufs + (i % 3) * 4096, Whp_p + i * 2048,
                                    Wr1_p + i * 2048, acc_a, acc_r, plbase, cc);
            }
            #pragma unroll
            for (int ci = 0; ci < 2; ci++)
                #pragma unroll
                for (int p = 0; p < 2; p++) {
                    float2 f = unpack2(acc_a[ci * 2 + p]);
                    *(float2*)(g_cat + catbase + (c0 + cc + ci) * 64 + (plbase + p) * 2)
                        = make_float2(tanhf(f.x), tanhf(f.y));
                }
            // S4 reduce: v[row] = sum_cols relu(acc)*Wr2[col]
            {
                float w20 = bias_s[160 + cc], w21 = bias_s[160 + cc + 1];
                float2 r00 = unpack2(acc_r[0]), r10 = unpack2(acc_r[1]);
                float2 r01 = unpack2(acc_r[2]), r11 = unpack2(acc_r[3]);
                float v0 = fmaxf(r00.x, 0.f) * w20 + fmaxf(r01.x, 0.f) * w21;
                float v1 = fmaxf(r00.y, 0.f) * w20 + fmaxf(r01.y, 0.f) * w21;
                float v2 = fmaxf(r10.x, 0.f) * w20 + fmaxf(r11.x, 0.f) * w21;
                float v3 = fmaxf(r10.y, 0.f) * w20 + fmaxf(r11.y, 0.f) * w21;
                #pragma unroll
                for (int off = 1; off <= 2; off <<= 1) {
                    v0 += __shfl_xor_sync(0xffffffffu, v0, off);
                    v1 += __shfl_xor_sync(0xffffffffu, v1, off);
                    v2 += __shfl_xor_sync(0xffffffffu, v2, off);
                    v3 += __shfl_xor_sync(0xffffffffu, v3, off);
                }
                if (lc == 0)
                    *(float4*)(g_r1p2 + (bj * 4 + wc) * NBATCH + row0 + wr * 32 + lr * 4)
                        = make_float4(v0, v1, v2, v3);
            }
        } else {
            // h0 == 0 -> cat[:,0:256] = tanh(bhp), uniform over rows
            #pragma unroll
            for (int ci = 0; ci < 2; ci++) {
                float av = tanhf(bias_s[cc + ci]);
                #pragma unroll
                for (int p = 0; p < 2; p++)
                    *(float2*)(g_cat + catbase + (c0 + cc + ci) * 64 + (plbase + p) * 2)
                        = make_float2(av, av);
            }
        }
        group_barrier(bi);

        // ================= Phase B: m = tanh(cat @ Wm + bm) =================
        // finalize out[t-1] first so its L2 latency overlaps the GEMM
        if (bj == 0 && t > 0 && tid < BM) {
            int n = row0 + tid;
            float s = br2v;
            #pragma unroll 8
            for (int q = 0; q < 32; q++)
                s += __ldcg(&g_r1p2[q * NBATCH + n]);
            out[(size_t)(t - 1) * NBATCH + n] = s;
        }
        {
            u64 acc[4];
            acc[0] = acc[1] = dup2(bias_s[64 + cc]);
            acc[2] = acc[3] = dup2(bias_s[64 + cc + 1]);
            gemm_pipe<8, false>(g_cat + catbase, Wm_p, Wm_p, bufs, acc, acc, plbase, cc);
            #pragma unroll
            for (int ci = 0; ci < 2; ci++)
                #pragma unroll
                for (int p = 0; p < 2; p++) {
                    float2 f = unpack2(acc[ci * 2 + p]);
                    *(float2*)(g_m + hbase + (c0 + cc + ci) * 64 + (plbase + p) * 2)
                        = make_float2(tanhf(f.x), tanhf(f.y));
                }
        }
        group_barrier(bi);

        // ================= Phase C: h = tanh(m @ Whpost + bhpost) ============
        {
            u64 acc[4];
            acc[0] = acc[1] = dup2(bias_s[96 + cc]);
            acc[2] = acc[3] = dup2(bias_s[96 + cc + 1]);
            gemm_pipe<4, false>(g_m + hbase, Whpost_p, Whpost_p, bufs, acc, acc, plbase, cc);
            #pragma unroll
            for (int ci = 0; ci < 2; ci++)
                #pragma unroll
                for (int p = 0; p < 2; p++) {
                    float2 f = unpack2(acc[ci * 2 + p]);
                    *(float2*)(g_h + hbase + (c0 + cc + ci) * 64 + (plbase + p) * 2)
                        = make_float2(tanhf(f.x), tanhf(f.y));
                }
        }
        group_barrier(bi);
    }

    // ================= Epilogue: regressor for final step =================
    {
        u64 acc[4];
        acc[0] = acc[1] = dup2(bias_s[128 + cc]);
        acc[2] = acc[3] = dup2(bias_s[128 + cc + 1]);
        gemm_pipe<4, false>(g_h + hbase, Wr1_p, Wr1_p, bufs, acc, acc, plbase, cc);
        float w20 = bias_s[160 + cc], w21 = bias_s[160 + cc + 1];
        float2 r00 = unpack2(acc[0]), r10 = unpack2(acc[1]);
        float2 r01 = unpack2(acc[2]), r11 = unpack2(acc[3]);
        float v0 = fmaxf(r00.x, 0.f) * w20 + fmaxf(r01.x, 0.f) * w21;
        float v1 = fmaxf(r00.y, 0.f) * w20 + fmaxf(r01.y, 0.f) * w21;
        float v2 = fmaxf(r10.x, 0.f) * w20 + fmaxf(r11.x, 0.f) * w21;
        float v3 = fmaxf(r10.y, 0.f) * w20 + fmaxf(r11.y, 0.f) * w21;
        #pragma unroll
        for (int off = 1; off <= 2; off <<= 1) {
            v0 += __shfl_xor_sync(0xffffffffu, v0, off);
            v1 += __shfl_xor_sync(0xffffffffu, v1, off);
            v2 += __shfl_xor_sync(0xffffffffu, v2, off);
            v3 += __shfl_xor_sync(0xffffffffu, v3, off);
        }
        if (lc == 0)
            *(float4*)(g_r1p2 + (bj * 4 + wc) * NBATCH + row0 + wr * 32 + lr * 4)
                = make_float4(v0, v1, v2, v3);
    }
    group_barrier(bi);
    if (bj == 0 && tid < BM) {
        int n = row0 + tid;
        float s = br2v;
        #pragma unroll 8
        for (int q = 0; q < 32; q++)
            s += __ldcg(&g_r1p2[q * NBATCH + n]);
        out[(size_t)(T_STEPS - 1) * NBATCH + n] = s;
    }
}

extern "C" void kernel_launch(void* const* d_in, const int* in_sizes, int n_in,
                              void* d_out, int out_size)
{
    (void)in_sizes; (void)n_in; (void)out_size;
    const float* inputs = (const float*)d_in[0];
    const float* Whp    = (const float*)d_in[1];
    const float* bhp    = (const float*)d_in[2];
    const float* Wcp    = (const float*)d_in[3];
    const float* bcp    = (const float*)d_in[4];
    const float* Wm     = (const float*)d_in[5];
    const float* bm     = (const float*)d_in[6];
    const float* Whpost = (const float*)d_in[7];
    const float* bhpost = (const float*)d_in[8];
    const float* Wr1    = (const float*)d_in[9];
    const float* br1    = (const float*)d_in[10];
    const float* Wr2    = (const float*)d_in[11];
    const float* br2    = (const float*)d_in[12];
    float* out = (float*)d_out;

    // smem: packed weights 43008 + bias 192 + 3x4096 staging = 55488 floats
    const size_t smem_bytes = (size_t)55488 * sizeof(float);
    cudaFuncSetAttribute(recurrent_kernel,
                         cudaFuncAttributeMaxDynamicSharedMemorySize,
                         (int)smem_bytes);

    recurrent_kernel<<<NCTA, NTHR, smem_bytes>>>(
        inputs, Whp, bhp, Wcp, bcp, Wm, bm, Whpost, bhpost,
        Wr1, br1, Wr2, br2, out);
}

// round 16
// speedup vs baseline: 2.7837x; 1.7734x over previous
#include <cuda_runtime.h>
#include <math.h>
#include <stdint.h>

// Problem constants
#define T_STEPS 512
#define NBATCH  1024
#define IDIM    64
#define RDIM    256
#define NCTA    128
#define NTHR    256
#define NGRP    16

// ---------------- fragment-major activation buffers ----------------
// layout: [plane][bi][kt][mt][lane][4] u32   (plane0=bf16-hi pairs, plane1=lo)
// one (kt,mt) tile = 16 rows x 16 cols, matching mma.m16n8k16 A-fragments.
#define PS_H   (16*16*512)    // plane stride for h / m  (16 ktiles)
#define PS_CAT (16*32*512)    // plane stride for cat    (32 ktiles)
__device__ unsigned g_hF[2 * 16 * 16 * 4 * 32 * 4];
__device__ unsigned g_catF[2 * 16 * 32 * 4 * 32 * 4];
__device__ unsigned g_mF[2 * 16 * 16 * 4 * 32 * 4];
__device__ float    g_r1p[16 * NBATCH];        // regressor partials [bj*2+q][n]
__device__ unsigned g_grp_bar[NGRP * 32];      // per-group barrier: cnt @+0, gen @+16

// ---------------- bf16 pack/split helpers ----------------
__device__ __forceinline__ unsigned packbf(float lo, float hi) {
    unsigned r;
    asm("cvt.rn.bf16x2.f32 %0, %1, %2;" : "=r"(r) : "f"(hi), "f"(lo));
    return r;
}
__device__ __forceinline__ float bflo2f(unsigned u) { return __uint_as_float(u << 16); }
__device__ __forceinline__ float bfhi2f(unsigned u) { return __uint_as_float(u & 0xffff0000u); }
__device__ __forceinline__ void split2(float f0, float f1, unsigned& hi, unsigned& lo) {
    hi = packbf(f0, f1);
    lo = packbf(f0 - bflo2f(hi), f1 - bfhi2f(hi));
}

// ---------------- mma / ldg helpers ----------------
__device__ __forceinline__ void mma_bf(float& d0, float& d1, float& d2, float& d3,
                                       const unsigned a[4], unsigned b0, unsigned b1) {
    asm("mma.sync.aligned.m16n8k16.row.col.f32.bf16.bf16.f32 "
        "{%0,%1,%2,%3},{%4,%5,%6,%7},{%8,%9},{%0,%1,%2,%3};"
        : "+f"(d0), "+f"(d1), "+f"(d2), "+f"(d3)
        : "r"(a[0]), "r"(a[1]), "r"(a[2]), "r"(a[3]), "r"(b0), "r"(b1));
}
__device__ __forceinline__ void ldg4cg(unsigned a[4], const unsigned* p) {
    asm("ld.global.cg.v4.u32 {%0,%1,%2,%3}, [%4];"
        : "=r"(a[0]), "=r"(a[1]), "=r"(a[2]), "=r"(a[3]) : "l"(p));
}

// ---------------- per-row-group barrier (8 CTAs) ----------------
__device__ __forceinline__ void group_barrier(int grp) {
    __threadfence();
    __syncthreads();
    if (threadIdx.x == 0) {
        unsigned* cnt = &g_grp_bar[grp * 32];
        unsigned* gen = &g_grp_bar[grp * 32 + 16];
        unsigned g = *((volatile unsigned*)gen);
        unsigned old = atomicAdd(cnt, 1u);
        if (old == 7) {
            *cnt = 0;
            __threadfence();
            *((volatile unsigned*)gen) = g + 1;
        } else {
            unsigned cur;
            do {
                asm volatile("ld.acquire.gpu.global.u32 %0, [%1];"
                             : "=r"(cur) : "l"(gen));
            } while (cur == g);
        }
    }
    __syncthreads();
}

// ---------------- split-bf16 GEMM over NKT ktiles ----------------
// Warp (mt,q) computes a 16-row x 16-col tile (ntiles 2q, 2q+1).
// D ≈ A·W: 3 mma per (kt, nt): Ah·Bh + Ah·Bl + Al·Bh.
template<int NKT, bool FUSE2>
__device__ __forceinline__ void gemm_tc(
    const unsigned* __restrict__ Abase, int PS,
    const unsigned* __restrict__ W1, const unsigned* __restrict__ W2,
    float* Da, float* Dr, int mt, int q, int lane)
{
    #pragma unroll 2
    for (int kt = 0; kt < NKT; kt++) {
        unsigned Ah[4], Al[4];
        const unsigned* pa = Abase + (kt * 4 + mt) * 128 + lane * 4;
        ldg4cg(Ah, pa);
        ldg4cg(Al, pa + PS);
        #pragma unroll
        for (int j = 0; j < 2; j++) {
            const int nt = 2 * q + j;
            const unsigned* pb = W1 + ((kt * 8 + nt) * 32 + lane) * 2;       // hi plane
            const unsigned* pl = W1 + ((kt * 8 + 4 + nt) * 32 + lane) * 2;   // lo plane
            unsigned bh0 = pb[0], bh1 = pb[1], bl0 = pl[0], bl1 = pl[1];
            float* D = Da + 4 * j;
            mma_bf(D[0], D[1], D[2], D[3], Ah, bh0, bh1);
            mma_bf(D[0], D[1], D[2], D[3], Ah, bl0, bl1);
            mma_bf(D[0], D[1], D[2], D[3], Al, bh0, bh1);
            if (FUSE2) {
                const unsigned* qb = W2 + ((kt * 8 + nt) * 32 + lane) * 2;
                const unsigned* ql = W2 + ((kt * 8 + 4 + nt) * 32 + lane) * 2;
                unsigned ch0 = qb[0], ch1 = qb[1], cl0 = ql[0], cl1 = ql[1];
                float* R = Dr + 4 * j;
                mma_bf(R[0], R[1], R[2], R[3], Ah, ch0, ch1);
                mma_bf(R[0], R[1], R[2], R[3], Ah, cl0, cl1);
                mma_bf(R[0], R[1], R[2], R[3], Al, ch0, ch1);
            }
        }
    }
}

// bias init: D[0..3] = nt0 (cols q*16+2tig,+1), D[4..7] = nt1 (cols +8)
__device__ __forceinline__ void init_bias(float* D, const float* b, int q, int tig) {
    int cb0 = q * 16 + 2 * tig;
    D[0] = b[cb0];     D[1] = b[cb0 + 1]; D[2] = D[0]; D[3] = D[1];
    D[4] = b[cb0 + 8]; D[5] = b[cb0 + 9]; D[6] = D[4]; D[7] = D[5];
}

// tanh + hi/lo split + store next-GEMM A-fragment (C-frags ARE A-frags)
__device__ __forceinline__ void store_tanh(unsigned* dst, int PS, const float* D) {
    unsigned H[4], L[4];
    split2(tanhf(D[0]), tanhf(D[1]), H[0], L[0]);   // a0: row g,   k-lo
    split2(tanhf(D[2]), tanhf(D[3]), H[1], L[1]);   // a1: row g+8, k-lo
    split2(tanhf(D[4]), tanhf(D[5]), H[2], L[2]);   // a2: row g,   k-hi
    split2(tanhf(D[6]), tanhf(D[7]), H[3], L[3]);   // a3: row g+8, k-hi
    *(uint4*)dst        = make_uint4(H[0], H[1], H[2], H[3]);
    *(uint4*)(dst + PS) = make_uint4(L[0], L[1], L[2], L[3]);
}

__global__ void __launch_bounds__(NTHR, 1)
recurrent_kernel(const float* __restrict__ inputs,
                 const float* __restrict__ Whp, const float* __restrict__ bhp,
                 const float* __restrict__ Wcp, const float* __restrict__ bcp,
                 const float* __restrict__ Wm,  const float* __restrict__ bm,
                 const float* __restrict__ Whpost, const float* __restrict__ bhpost,
                 const float* __restrict__ Wr1, const float* __restrict__ br1,
                 const float* __restrict__ Wr2, const float* __restrict__ br2,
                 float* __restrict__ out)
{
    extern __shared__ unsigned smemu[];
    unsigned* Whp_f    = smemu;             // 16kt * 512 = 8192
    unsigned* Wr1_f    = smemu + 8192;
    unsigned* Whpost_f = smemu + 16384;
    unsigned* Wm_f     = smemu + 24576;     // 32kt -> 16384
    unsigned* Wcp_f    = smemu + 40960;     // 4kt  -> 2048
    float*    bias_s   = (float*)(smemu + 43008);   // 192 floats

    const int tid  = threadIdx.x;
    const int wid  = tid >> 5;
    const int lane = tid & 31;
    const int gid  = lane >> 2;
    const int tig  = lane & 3;
    const int mt   = wid >> 1;     // m-tile 0..3 (16 rows each)
    const int q    = wid & 1;      // ntile-pair: nt = 2q, 2q+1

    const int bi   = blockIdx.x >> 3;   // row group 0..15
    const int bj   = blockIdx.x & 7;    // col tile 0..7
    const int row0 = bi * 64;
    const int c0   = bj * 32;
    const int ktw  = bj * 2 + q;        // ktile this warp produces

    // ---- preprocess weights into B-fragment hi/lo planes in smem ----
    // dst[((kt*8 + plane*4 + nt)*32 + lane)*2 + reg]
    {
        const float* Ws[5]  = {Whp, Wr1, Whpost, Wm, Wcp};
        unsigned*    Wd[5]  = {Whp_f, Wr1_f, Whpost_f, Wm_f, Wcp_f};
        const int    KT[5]  = {16, 16, 16, 32, 4};
        for (int w = 0; w < 5; w++) {
            const float* W = Ws[w];
            unsigned* dst = Wd[w];
            int total = KT[w] * 512;
            for (int idx = tid; idx < total; idx += NTHR) {
                int reg = idx & 1, ln = (idx >> 1) & 31, nt = (idx >> 6) & 3;
                int plane = (idx >> 8) & 1, kt = idx >> 9;
                int g2 = ln >> 2, t2 = ln & 3;
                int n = c0 + nt * 8 + g2;
                int k = kt * 16 + reg * 8 + 2 * t2;
                float v0 = W[k * RDIM + n], v1 = W[(k + 1) * RDIM + n];
                unsigned hi = packbf(v0, v1);
                unsigned val = plane ? packbf(v0 - bflo2f(hi), v1 - bfhi2f(hi)) : hi;
                dst[((kt * 8 + plane * 4 + nt) * 32 + ln) * 2 + reg] = val;
            }
        }
        if (tid < 32) {
            bias_s[tid]       = bhp[c0 + tid];
            bias_s[32 + tid]  = bcp[c0 + tid];
            bias_s[64 + tid]  = bm[c0 + tid];
            bias_s[96 + tid]  = bhpost[c0 + tid];
            bias_s[128 + tid] = br1[c0 + tid];
            bias_s[160 + tid] = Wr2[c0 + tid];
        }
    }
    const float br2v = __ldg(br2);
    __syncthreads();

    for (int t = 0; t < T_STEPS; t++) {
        // ================= Phase A =================
        // ---- S0: tcp = tanh(x @ Wcp + bcp) -> catF ktiles 16..31 ----
        {
            float Dx[8];
            init_bias(Dx, bias_s + 32, q, tig);
            const float* xg = inputs + (size_t)t * NBATCH * IDIM + (size_t)row0 * IDIM;
            #pragma unroll
            for (int kt = 0; kt < 4; kt++) {
                const float* p0 = xg + (mt * 16 + gid) * IDIM + kt * 16 + 2 * tig;
                float2 x00 = *(const float2*)p0;
                float2 x01 = *(const float2*)(p0 + 8);
                float2 x10 = *(const float2*)(p0 + 8 * IDIM);
                float2 x11 = *(const float2*)(p0 + 8 * IDIM + 8);
                unsigned Ah[4], Al[4];
                split2(x00.x, x00.y, Ah[0], Al[0]);
                split2(x10.x, x10.y, Ah[1], Al[1]);
                split2(x01.x, x01.y, Ah[2], Al[2]);
                split2(x11.x, x11.y, Ah[3], Al[3]);
                #pragma unroll
                for (int j = 0; j < 2; j++) {
                    int nt = 2 * q + j;
                    const unsigned* pb = Wcp_f + ((kt * 8 + nt) * 32 + lane) * 2;
                    const unsigned* pl = Wcp_f + ((kt * 8 + 4 + nt) * 32 + lane) * 2;
                    unsigned bh0 = pb[0], bh1 = pb[1], bl0 = pl[0], bl1 = pl[1];
                    float* D = Dx + 4 * j;
                    mma_bf(D[0], D[1], D[2], D[3], Ah, bh0, bh1);
                    mma_bf(D[0], D[1], D[2], D[3], Ah, bl0, bl1);
                    mma_bf(D[0], D[1], D[2], D[3], Al, bh0, bh1);
                }
            }
            unsigned* dst = g_catF + (size_t)((bi * 32 + 16 + ktw) * 512 + mt * 128 + lane * 4);
            store_tanh(dst, PS_CAT, Dx);
        }

        if (t > 0) {
            // ---- S1 + S4: a = tanh(h@Whp+b); r1 = h@Wr1+b ----
            float Da[8], Dr[8];
            init_bias(Da, bias_s, q, tig);
            init_bias(Dr, bias_s + 128, q, tig);
            gemm_tc<16, true>(g_hF + bi * 8192, PS_H, Whp_f, Wr1_f, Da, Dr, mt, q, lane);
            unsigned* dst = g_catF + (size_t)((bi * 32 + ktw) * 512 + mt * 128 + lane * 4);
            store_tanh(dst, PS_CAT, Da);
            // S4 partials: v[row] = sum_cols relu(r)*Wr2[col]
            float w20 = bias_s[160 + q * 16 + 2 * tig], w21 = bias_s[161 + q * 16 + 2 * tig];
            float w22 = bias_s[168 + q * 16 + 2 * tig], w23 = bias_s[169 + q * 16 + 2 * tig];
            float vlo = fmaxf(Dr[0], 0.f) * w20 + fmaxf(Dr[1], 0.f) * w21
                      + fmaxf(Dr[4], 0.f) * w22 + fmaxf(Dr[5], 0.f) * w23;
            float vhi = fmaxf(Dr[2], 0.f) * w20 + fmaxf(Dr[3], 0.f) * w21
                      + fmaxf(Dr[6], 0.f) * w22 + fmaxf(Dr[7], 0.f) * w23;
            vlo += __shfl_xor_sync(0xffffffffu, vlo, 1);
            vlo += __shfl_xor_sync(0xffffffffu, vlo, 2);
            vhi += __shfl_xor_sync(0xffffffffu, vhi, 1);
            vhi += __shfl_xor_sync(0xffffffffu, vhi, 2);
            if (tig == 0) {
                int base = ktw * NBATCH + row0 + mt * 16 + gid;
                g_r1p[base]     = vlo;
                g_r1p[base + 8] = vhi;
            }
        } else {
            // h0 == 0 -> cat lo-tiles = tanh(bhp), uniform over rows
            float Da[8];
            init_bias(Da, bias_s, q, tig);
            unsigned* dst = g_catF + (size_t)((bi * 32 + ktw) * 512 + mt * 128 + lane * 4);
            store_tanh(dst, PS_CAT, Da);
        }
        group_barrier(bi);

        // ================= Phase B: m = tanh(cat @ Wm + bm) =================
        if (bj == 0 && t > 0 && tid < 64) {
            int n = row0 + tid;
            float s = br2v;
            #pragma unroll
            for (int b = 0; b < 16; b++)
                s += __ldcg(&g_r1p[b * NBATCH + n]);
            out[(size_t)(t - 1) * NBATCH + n] = s;
        }
        {
            float Dm[8];
            init_bias(Dm, bias_s + 64, q, tig);
            gemm_tc<32, false>(g_catF + bi * 16384, PS_CAT, Wm_f, Wm_f, Dm, Dm, mt, q, lane);
            unsigned* dst = g_mF + (size_t)((bi * 16 + ktw) * 512 + mt * 128 + lane * 4);
            store_tanh(dst, PS_H, Dm);
        }
        group_barrier(bi);

        // ================= Phase C: h = tanh(m @ Whpost + b) =================
        {
            float Dh[8];
            init_bias(Dh, bias_s + 96, q, tig);
            gemm_tc<16, false>(g_mF + bi * 8192, PS_H, Whpost_f, Whpost_f, Dh, Dh, mt, q, lane);
            unsigned* dst = g_hF + (size_t)((bi * 16 + ktw) * 512 + mt * 128 + lane * 4);
            store_tanh(dst, PS_H, Dh);
        }
        group_barrier(bi);
    }

    // ================= Epilogue: regressor for final step =================
    {
        float Dr[8];
        init_bias(Dr, bias_s + 128, q, tig);
        gemm_tc<16, false>(g_hF + bi * 8192, PS_H, Wr1_f, Wr1_f, Dr, Dr, mt, q, lane);
        float w20 = bias_s[160 + q * 16 + 2 * tig], w21 = bias_s[161 + q * 16 + 2 * tig];
        float w22 = bias_s[168 + q * 16 + 2 * tig], w23 = bias_s[169 + q * 16 + 2 * tig];
        float vlo = fmaxf(Dr[0], 0.f) * w20 + fmaxf(Dr[1], 0.f) * w21
                  + fmaxf(Dr[4], 0.f) * w22 + fmaxf(Dr[5], 0.f) * w23;
        float vhi = fmaxf(Dr[2], 0.f) * w20 + fmaxf(Dr[3], 0.f) * w21
                  + fmaxf(Dr[6], 0.f) * w22 + fmaxf(Dr[7], 0.f) * w23;
        vlo += __shfl_xor_sync(0xffffffffu, vlo, 1);
        vlo += __shfl_xor_sync(0xffffffffu, vlo, 2);
        vhi += __shfl_xor_sync(0xffffffffu, vhi, 1);
        vhi += __shfl_xor_sync(0xffffffffu, vhi, 2);
        if (tig == 0) {
            int base = ktw * NBATCH + row0 + mt * 16 + gid;
            g_r1p[base]     = vlo;
            g_r1p[base + 8] = vhi;
        }
    }
    group_barrier(bi);
    if (bj == 0 && tid < 64) {
        int n = row0 + tid;
        float s = br2v;
        #pragma unroll
        for (int b = 0; b < 16; b++)
            s += __ldcg(&g_r1p[b * NBATCH + n]);
        out[(size_t)(T_STEPS - 1) * NBATCH + n] = s;
    }
}

extern "C" void kernel_launch(void* const* d_in, const int* in_sizes, int n_in,
                              void* d_out, int out_size)
{
    (void)in_sizes; (void)n_in; (void)out_size;
    const float* inputs = (const float*)d_in[0];
    const float* Whp    = (const float*)d_in[1];
    const float* bhp    = (const float*)d_in[2];
    const float* Wcp    = (const float*)d_in[3];
    const float* bcp    = (const float*)d_in[4];
    const float* Wm     = (const float*)d_in[5];
    const float* bm     = (const float*)d_in[6];
    const float* Whpost = (const float*)d_in[7];
    const float* bhpost = (const float*)d_in[8];
    const float* Wr1    = (const float*)d_in[9];
    const float* br1    = (const float*)d_in[10];
    const float* Wr2    = (const float*)d_in[11];
    const float* br2    = (const float*)d_in[12];
    float* out = (float*)d_out;

    // smem: fragment weights 43008 u32 + 192 floats bias = 172,800 B
    const size_t smem_bytes = (size_t)43200 * 4;
    cudaFuncSetAttribute(recurrent_kernel,
                         cudaFuncAttributeMaxDynamicSharedMemorySize,
                         (int)smem_bytes);

    recurrent_kernel<<<NCTA, NTHR, smem_bytes>>>(
        inputs, Whp, bhp, Wcp, bcp, Wm, bm, Whpost, bhpost,
        Wr1, br1, Wr2, br2, out);
}